// round 1
// baseline (speedup 1.0000x reference)
#include <cuda_runtime.h>
#include <math.h>

#define B_ 8
#define N_ 19
#define T_ 1000
#define D_ 512
#define NLAYERS 2
#define ALPHA 0.05f
#define LN_EPS 1e-5f
#define ROW_EPS 1e-6f

// Fused GraphChannelMixer: one CTA per (b, t) pair.
// State x (19 x 512) lives in SMEM across both layers.
// Dynamic SMEM: xs (current x) + xb (mixed / pre-LN buffer) = 2*19*512 floats.
__global__ __launch_bounds__(256, 2)
void gcm_kernel(const float* __restrict__ features,
                const float* __restrict__ adjacency,
                const float* __restrict__ edge_w,
                const float* __restrict__ edge_b,
                const float* __restrict__ W,
                const float* __restrict__ bias,
                const float* __restrict__ gamma,
                const float* __restrict__ beta,
                float* __restrict__ out)
{
    extern __shared__ float sm[];
    float (*xs)[D_] = (float (*)[D_])sm;             // current x
    float (*xb)[D_] = (float (*)[D_])(sm + N_ * D_); // mixed / pre-LN buffer
    __shared__ float adjn[N_][N_];

    const int blk = blockIdx.x;
    const int b = blk / T_;
    const int t = blk % T_;
    const int tid = threadIdx.x;

    // ---- load x = features[b, :, t, :]  (layout (B,N,T,D)) ----
    const long fbase = (long)b * N_ * T_ * D_ + (long)t * D_;
    for (int idx = tid; idx < N_ * D_; idx += 256) {
        int n = idx >> 9;
        int d = idx & (D_ - 1);
        xs[n][d] = features[fbase + (long)n * T_ * D_ + d];
    }

    // ---- edge transform + softplus ----
    const float ew = edge_w[0];
    const float eb = edge_b[0];
    const float* adj = adjacency + ((long)b * T_ + t) * (N_ * N_);
    for (int idx = tid; idx < N_ * N_; idx += 256) {
        float v = fmaf(adj[idx], ew, eb);
        // stable softplus: max(v,0) + log1p(exp(-|v|))
        float sp = fmaxf(v, 0.0f) + log1pf(expf(-fabsf(v)));
        adjn[idx / N_][idx % N_] = sp;
    }
    __syncthreads();

    // ---- row-normalize adjacency ----
    if (tid < N_) {
        float s = 0.0f;
        #pragma unroll
        for (int j = 0; j < N_; j++) s += adjn[tid][j];
        float inv = 1.0f / (s + ROW_EPS);
        #pragma unroll
        for (int j = 0; j < N_; j++) adjn[tid][j] *= inv;
    }
    __syncthreads();

    const int wid = tid >> 5;
    const int lane = tid & 31;
    const int c0 = 2 * tid;  // this thread's two output columns

    for (int l = 0; l < NLAYERS; l++) {
        // ---- neighbor mixing: xb = (1-a)*xs + a*(adjn @ xs) ----
        for (int idx = tid; idx < N_ * D_; idx += 256) {
            int i = idx >> 9;
            int d = idx & (D_ - 1);
            float acc = 0.0f;
            #pragma unroll
            for (int j = 0; j < N_; j++) acc = fmaf(adjn[i][j], xs[j][d], acc);
            xb[i][d] = (1.0f - ALPHA) * xs[i][d] + ALPHA * acc;
        }
        __syncthreads();

        // ---- GEMM: y[i][c] = sum_k xb[i][k] * W[l][k][c] + b[l][c] ----
        // thread owns columns (c0, c0+1), all 19 rows.
        const float* Wl = W + (long)l * D_ * D_;
        float2 acc[N_];
        {
            float b0 = bias[l * D_ + c0];
            float b1 = bias[l * D_ + c0 + 1];
            #pragma unroll
            for (int i = 0; i < N_; i++) { acc[i].x = b0; acc[i].y = b1; }
        }
        #pragma unroll 2
        for (int k = 0; k < D_; k++) {
            float2 w = *reinterpret_cast<const float2*>(Wl + (long)k * D_ + c0);
            #pragma unroll
            for (int i = 0; i < N_; i++) {
                float s = xb[i][k];  // SMEM broadcast across warp
                acc[i].x = fmaf(s, w.x, acc[i].x);
                acc[i].y = fmaf(s, w.y, acc[i].y);
            }
        }
        __syncthreads();  // all GEMM reads of xb done before overwriting it

        // residual add (xs still holds pre-layer x), stash y in xb
        #pragma unroll
        for (int i = 0; i < N_; i++) {
            xb[i][c0]     = acc[i].x + xs[i][c0];
            xb[i][c0 + 1] = acc[i].y + xs[i][c0 + 1];
        }
        __syncthreads();

        // ---- LayerNorm + exact GELU, one warp per row ----
        for (int r = wid; r < N_; r += 8) {
            float sum = 0.0f, sq = 0.0f;
            #pragma unroll
            for (int d = lane; d < D_; d += 32) {
                float v = xb[r][d];
                sum += v;
                sq = fmaf(v, v, sq);
            }
            #pragma unroll
            for (int o = 16; o; o >>= 1) {
                sum += __shfl_xor_sync(0xffffffffu, sum, o);
                sq  += __shfl_xor_sync(0xffffffffu, sq, o);
            }
            float mu = sum * (1.0f / D_);
            float var = sq * (1.0f / D_) - mu * mu;   // population variance
            float rstd = rsqrtf(var + LN_EPS);
            #pragma unroll
            for (int d = lane; d < D_; d += 32) {
                float v = (xb[r][d] - mu) * rstd;
                v = fmaf(v, gamma[l * D_ + d], beta[l * D_ + d]);
                // exact GELU: 0.5*x*(1+erf(x/sqrt(2)))
                float g = 0.5f * v * (1.0f + erff(v * 0.70710678118654752f));
                xs[r][d] = g;
            }
        }
        __syncthreads();
    }

    // ---- write out, layout (B,N,T,D) == features layout ----
    for (int idx = tid; idx < N_ * D_; idx += 256) {
        int n = idx >> 9;
        int d = idx & (D_ - 1);
        out[fbase + (long)n * T_ * D_ + d] = xs[n][d];
    }
}

extern "C" void kernel_launch(void* const* d_in, const int* in_sizes, int n_in,
                              void* d_out, int out_size)
{
    const float* features  = (const float*)d_in[0];
    const float* adjacency = (const float*)d_in[1];
    const float* edge_w    = (const float*)d_in[2];
    const float* edge_b    = (const float*)d_in[3];
    const float* W         = (const float*)d_in[4];
    const float* bias      = (const float*)d_in[5];
    const float* gamma     = (const float*)d_in[6];
    const float* beta      = (const float*)d_in[7];
    float* out = (float*)d_out;

    size_t smem = (size_t)(2 * N_ * D_) * sizeof(float);  // 77824 B
    cudaFuncSetAttribute(gcm_kernel,
                         cudaFuncAttributeMaxDynamicSharedMemorySize,
                         (int)smem);
    gcm_kernel<<<B_ * T_, 256, smem>>>(features, adjacency, edge_w, edge_b,
                                       W, bias, gamma, beta, out);
}

// round 2
// speedup vs baseline: 1.1499x; 1.1499x over previous
#include <cuda_runtime.h>
#include <math.h>

#define B_ 8
#define N_ 19
#define T_ 1000
#define D_ 512
#define NLAYERS 2
#define ALPHA 0.05f
#define LN_EPS 1e-5f
#define ROW_EPS 1e-6f

#define NTHREADS 128
#define XT_STRIDE 22   // even (8B-aligned pairs), 22 mod 32 -> only 2-way STS conflicts

typedef unsigned long long u64;

// ---- packed fp32x2 helpers (sm_103a FFMA2 path, exact fp32) ----
__device__ __forceinline__ u64 pack2(float lo, float hi) {
    u64 r;
    asm("mov.b64 %0, {%1, %2};" : "=l"(r) : "f"(lo), "f"(hi));
    return r;
}
__device__ __forceinline__ void unpack2(u64 v, float& lo, float& hi) {
    asm("mov.b64 {%0, %1}, %2;" : "=f"(lo), "=f"(hi) : "l"(v));
}
__device__ __forceinline__ u64 ffma2(u64 a, u64 b, u64 c) {
    u64 d;
    asm("fma.rn.f32x2 %0, %1, %2, %3;" : "=l"(d) : "l"(a), "l"(b), "l"(c));
    return d;
}

// One CTA per (b, t) graph. State xs[19][512] fp32 in SMEM across both layers.
// GEMM uses a transposed mixed buffer xt[k][row] so row-pairs load as LDS.64
// and feed packed FFMA2. 128 threads; thread owns 4 output columns, all rows.
__global__ __launch_bounds__(NTHREADS, 2)
void gcm_kernel(const float* __restrict__ features,
                const float* __restrict__ adjacency,
                const float* __restrict__ edge_w,
                const float* __restrict__ edge_b,
                const float* __restrict__ W,
                const float* __restrict__ bias,
                const float* __restrict__ gamma,
                const float* __restrict__ beta,
                float* __restrict__ out)
{
    extern __shared__ float sm[];
    float (*xs)[D_] = (float (*)[D_])sm;                            // 19 x 512
    float (*xt)[XT_STRIDE] = (float (*)[XT_STRIDE])(sm + N_ * D_);  // 512 x 22
    __shared__ float adjn[N_][N_];

    const int blk = blockIdx.x;
    const int b = blk / T_;
    const int t = blk % T_;
    const int tid = threadIdx.x;

    // zero the pad row (row 19) of xt once; never written afterwards
    for (int k = tid; k < D_; k += NTHREADS) xt[k][N_] = 0.0f;

    // ---- load x = features[b, :, t, :]  (layout (B,N,T,D)) ----
    const long fbase = (long)b * N_ * T_ * D_ + (long)t * D_;
    for (int idx = tid; idx < N_ * D_; idx += NTHREADS) {
        int n = idx >> 9;
        int d = idx & (D_ - 1);
        xs[n][d] = features[fbase + (long)n * T_ * D_ + d];
    }

    // ---- edge transform (Linear(1,1)) + stable softplus ----
    const float ew = edge_w[0];
    const float eb = edge_b[0];
    const float* adj = adjacency + ((long)b * T_ + t) * (N_ * N_);
    for (int idx = tid; idx < N_ * N_; idx += NTHREADS) {
        float v = fmaf(adj[idx], ew, eb);
        float sp = fmaxf(v, 0.0f) + log1pf(expf(-fabsf(v)));
        adjn[idx / N_][idx % N_] = sp;
    }
    __syncthreads();

    // ---- row-normalize adjacency ----
    if (tid < N_) {
        float s = 0.0f;
        #pragma unroll
        for (int j = 0; j < N_; j++) s += adjn[tid][j];
        float inv = 1.0f / (s + ROW_EPS);
        #pragma unroll
        for (int j = 0; j < N_; j++) adjn[tid][j] *= inv;
    }
    __syncthreads();

    const int wid = tid >> 5;
    const int lane = tid & 31;
    const int c0 = tid << 2;  // 4 columns per thread

    for (int l = 0; l < NLAYERS; l++) {
        // ---- mixing: xt[d][i] = (1-a)*xs[i][d] + a * sum_j adjn[i][j]*xs[j][d]
        for (int idx = tid; idx < N_ * D_; idx += NTHREADS) {
            int i = idx >> 9;
            int d = idx & (D_ - 1);
            float a0 = 0.0f, a1 = 0.0f;  // 2-way split to shorten FMA chain
            #pragma unroll
            for (int j = 0; j < N_ - 1; j += 2) {
                a0 = fmaf(adjn[i][j],     xs[j][d],     a0);
                a1 = fmaf(adjn[i][j + 1], xs[j + 1][d], a1);
            }
            a0 = fmaf(adjn[i][N_ - 1], xs[N_ - 1][d], a0);
            xt[d][i] = (1.0f - ALPHA) * xs[i][d] + ALPHA * (a0 + a1);
        }
        __syncthreads();

        // ---- GEMM: y[r][c] = sum_k xt[k][r] * W[l][k][c] + bias[l][c]
        // acc[p][c] holds the packed pair (rows 2p, 2p+1) for column c0+c.
        const float* Wl = W + (long)l * D_ * D_;
        u64 acc[10][4];
        {
            float4 bv = *reinterpret_cast<const float4*>(bias + l * D_ + c0);
            u64 b0 = pack2(bv.x, bv.x), b1 = pack2(bv.y, bv.y);
            u64 b2 = pack2(bv.z, bv.z), b3 = pack2(bv.w, bv.w);
            #pragma unroll
            for (int p = 0; p < 10; p++) {
                acc[p][0] = b0; acc[p][1] = b1; acc[p][2] = b2; acc[p][3] = b3;
            }
        }
        #pragma unroll 2
        for (int k = 0; k < D_; k++) {
            float4 w = *reinterpret_cast<const float4*>(Wl + (long)k * D_ + c0);
            u64 w0 = pack2(w.x, w.x);
            u64 w1 = pack2(w.y, w.y);
            u64 w2 = pack2(w.z, w.z);
            u64 w3 = pack2(w.w, w.w);
            #pragma unroll
            for (int p = 0; p < 10; p++) {
                u64 xp = *reinterpret_cast<const u64*>(&xt[k][2 * p]);  // LDS.64 broadcast
                acc[p][0] = ffma2(xp, w0, acc[p][0]);
                acc[p][1] = ffma2(xp, w1, acc[p][1]);
                acc[p][2] = ffma2(xp, w2, acc[p][2]);
                acc[p][3] = ffma2(xp, w3, acc[p][3]);
            }
        }

        // ---- residual add in place on xs (each location owned by one thread)
        #pragma unroll
        for (int p = 0; p < 10; p++) {
            int r0 = 2 * p, r1 = 2 * p + 1;
            #pragma unroll
            for (int c = 0; c < 4; c++) {
                float lo, hi;
                unpack2(acc[p][c], lo, hi);
                xs[r0][c0 + c] += lo;
                if (r1 < N_) xs[r1][c0 + c] += hi;
            }
        }
        __syncthreads();

        // ---- LayerNorm + exact GELU, in place on xs; one warp per row ----
        for (int r = wid; r < N_; r += 4) {
            float sum = 0.0f, sq = 0.0f;
            #pragma unroll
            for (int d = lane; d < D_; d += 32) {
                float v = xs[r][d];
                sum += v;
                sq = fmaf(v, v, sq);
            }
            #pragma unroll
            for (int o = 16; o; o >>= 1) {
                sum += __shfl_xor_sync(0xffffffffu, sum, o);
                sq  += __shfl_xor_sync(0xffffffffu, sq, o);
            }
            float mu = sum * (1.0f / D_);
            float var = sq * (1.0f / D_) - mu * mu;  // population variance
            float rstd = rsqrtf(var + LN_EPS);
            #pragma unroll
            for (int d = lane; d < D_; d += 32) {
                float v = (xs[r][d] - mu) * rstd;
                v = fmaf(v, __ldg(gamma + l * D_ + d), __ldg(beta + l * D_ + d));
                float g = 0.5f * v * (1.0f + erff(v * 0.70710678118654752f));
                xs[r][d] = g;
            }
        }
        __syncthreads();
    }

    // ---- write out, layout (B,N,T,D) ----
    for (int idx = tid; idx < N_ * D_; idx += NTHREADS) {
        int n = idx >> 9;
        int d = idx & (D_ - 1);
        out[fbase + (long)n * T_ * D_ + d] = xs[n][d];
    }
}

extern "C" void kernel_launch(void* const* d_in, const int* in_sizes, int n_in,
                              void* d_out, int out_size)
{
    const float* features  = (const float*)d_in[0];
    const float* adjacency = (const float*)d_in[1];
    const float* edge_w    = (const float*)d_in[2];
    const float* edge_b    = (const float*)d_in[3];
    const float* W         = (const float*)d_in[4];
    const float* bias      = (const float*)d_in[5];
    const float* gamma     = (const float*)d_in[6];
    const float* beta      = (const float*)d_in[7];
    float* out = (float*)d_out;

    size_t smem = (size_t)(N_ * D_ + D_ * XT_STRIDE) * sizeof(float);  // 83968 B
    cudaFuncSetAttribute(gcm_kernel,
                         cudaFuncAttributeMaxDynamicSharedMemorySize,
                         (int)smem);
    gcm_kernel<<<B_ * T_, NTHREADS, smem>>>(features, adjacency, edge_w, edge_b,
                                            W, bias, gamma, beta, out);
}

// round 5
// speedup vs baseline: 2.2331x; 1.9420x over previous
#include <cuda_runtime.h>
#include <cuda_bf16.h>
#include <math.h>
#include <stdint.h>

#define B_ 8
#define N_ 19
#define T_ 1000
#define D_ 512
#define ALPHA 0.05f
#define LN_EPS 1e-5f
#define ROW_EPS 1e-6f

#define NGRAPH (B_ * T_)       // 8000
#define NROWS (NGRAPH * N_)    // 152000
#define MTILES 1188            // ceil(152000/128)
#define NTILES 4               // 512/128
#define KCHUNKS 8              // 512/64
#define ATILE_BYTES 16384      // 128 rows x 64 k x bf16 (swizzled)
#define BTILE_BYTES 16384      // 128 n   x 64 k x bf16 (swizzled)

// ---------------- scratch (__device__ globals; no runtime alloc) ------------
__device__ __align__(16) unsigned char g_ahi[(size_t)MTILES * KCHUNKS * ATILE_BYTES];
__device__ __align__(16) unsigned char g_alo[(size_t)MTILES * KCHUNKS * ATILE_BYTES];
__device__ __align__(16) unsigned char g_bhi[2 * KCHUNKS * NTILES * BTILE_BYTES];
__device__ __align__(16) unsigned char g_blo[2 * KCHUNKS * NTILES * BTILE_BYTES];
__device__ float g_adjn[(size_t)NGRAPH * N_ * N_];
__device__ float g_state[(size_t)MTILES * 128 * D_];
__device__ float g_y[(size_t)MTILES * 128 * D_];

// ---------------- helpers ---------------------------------------------------
__device__ __forceinline__ uint32_t swz(uint32_t o) { return o ^ ((o >> 3) & 0x70); }

__device__ __forceinline__ uint32_t smem_u32(const void* p) {
    uint32_t a;
    asm("{ .reg .u64 t; cvta.to.shared.u64 t, %1; cvt.u32.u64 %0, t; }" : "=r"(a) : "l"(p));
    return a;
}
__device__ __forceinline__ void bulk_g2s(uint32_t dst, const void* src,
                                         uint32_t bytes, uint32_t mbar) {
    asm volatile(
        "cp.async.bulk.shared::cta.global.mbarrier::complete_tx::bytes [%0], [%1], %2, [%3];"
        :: "r"(dst), "l"(src), "r"(bytes), "r"(mbar) : "memory");
}
#define MBAR_INIT(a, c) asm volatile("mbarrier.init.shared.b64 [%0], %1;" :: "r"(a), "r"(c) : "memory")
#define MBAR_EXPECT(a, b) asm volatile("mbarrier.arrive.expect_tx.shared.b64 _, [%0], %1;" :: "r"(a), "r"(b) : "memory")
#define MBAR_WAIT(addr, ph) do {                                                      \
    asm volatile(                                                                     \
        "{\n\t.reg .pred P;\n\t"                                                      \
        "WL_%=:\n\t"                                                                  \
        "mbarrier.try_wait.parity.acquire.cta.shared::cta.b64 P, [%0], %1, 0x989680;\n\t" \
        "@P bra.uni WD_%=;\n\t"                                                       \
        "bra.uni WL_%=;\n\t"                                                          \
        "WD_%=:\n\t}"                                                                 \
        :: "r"(addr), "r"(ph) : "memory");                                            \
} while (0)

#define LDX4(r, a)                                                                    \
    asm volatile("ldmatrix.sync.aligned.m8n8.x4.shared.b16 {%0,%1,%2,%3}, [%4];"      \
        : "=r"((r)[0]), "=r"((r)[1]), "=r"((r)[2]), "=r"((r)[3]) : "r"(a))

#define MMA(c, a, b0v, b1v)                                                           \
    asm volatile("mma.sync.aligned.m16n8k16.row.col.f32.bf16.bf16.f32 "               \
        "{%0,%1,%2,%3},{%4,%5,%6,%7},{%8,%9},{%0,%1,%2,%3};"                          \
        : "+f"((c)[0]), "+f"((c)[1]), "+f"((c)[2]), "+f"((c)[3])                      \
        : "r"((a)[0]), "r"((a)[1]), "r"((a)[2]), "r"((a)[3]), "r"(b0v), "r"(b1v))

// ---------------- stage 1: adjacency softplus + row-normalize ---------------
__global__ __launch_bounds__(128)
void adj_kernel(const float* __restrict__ adjacency,
                const float* __restrict__ edge_w, const float* __restrict__ edge_b)
{
    __shared__ float s[N_][N_];
    int g = blockIdx.x, tid = threadIdx.x;
    float ew = edge_w[0], eb = edge_b[0];
    const float* a = adjacency + (size_t)g * N_ * N_;
    for (int i = tid; i < N_ * N_; i += 128) {
        float v = fmaf(a[i], ew, eb);
        ((float*)s)[i] = fmaxf(v, 0.0f) + log1pf(expf(-fabsf(v)));
    }
    __syncthreads();
    if (tid < N_) {
        float sum = 0.0f;
        #pragma unroll
        for (int j = 0; j < N_; j++) sum += s[tid][j];
        float inv = 1.0f / (sum + ROW_EPS);
        #pragma unroll
        for (int j = 0; j < N_; j++) s[tid][j] *= inv;
    }
    __syncthreads();
    for (int i = tid; i < N_ * N_; i += 128)
        g_adjn[(size_t)g * N_ * N_ + i] = ((float*)s)[i];
}

// ---------------- stage 2: W -> bf16 hi/lo W^T tiles (n-major, swizzled) ----
__global__ __launch_bounds__(256)
void wconv_kernel(const float* __restrict__ W)
{
    int p = blockIdx.x * 256 + threadIdx.x;   // 2*512*64 tasks
    if (p >= 2 * 512 * 64) return;
    int l = p >> 15;
    int rem = p & 32767;
    int n = rem >> 6;
    int k8 = rem & 63;
    int k0 = k8 * 8;
    const float* src = W + (size_t)l * D_ * D_ + n;
    union { uint4 q; __nv_bfloat16 h[8]; } H, L;
    #pragma unroll
    for (int i = 0; i < 8; i++) {
        float w = src[(size_t)(k0 + i) * D_];
        H.h[i] = __float2bfloat16(w);
        L.h[i] = __float2bfloat16(w - __bfloat162float(H.h[i]));
    }
    int kchunk = k0 >> 6, nq = n >> 7, nl = n & 127, kl = k0 & 63;
    size_t blk = (size_t)l * (KCHUNKS * NTILES) + kchunk * NTILES + nq;
    uint32_t off = swz((uint32_t)(nl * 128 + kl * 2));
    *(uint4*)(g_bhi + blk * BTILE_BYTES + off) = H.q;
    *(uint4*)(g_blo + blk * BTILE_BYTES + off) = L.q;
}

// ---------------- stage 3: mixing + bf16 split -> swizzled A tiles ----------
__global__ __launch_bounds__(256)
void mix_kernel(const float* __restrict__ src, int transposed)
{
    __shared__ float xs[N_][D_];
    __shared__ float sadj[N_][N_];
    int g = blockIdx.x, tid = threadIdx.x;
    for (int i = tid; i < N_ * N_; i += 256)
        ((float*)sadj)[i] = g_adjn[(size_t)g * N_ * N_ + i];
    long tb = 0;
    if (transposed) {
        int bb = g / T_, tt = g - bb * T_;
        tb = (long)bb * N_ * T_ * D_ + (long)tt * D_;
    }
    for (int idx = tid; idx < N_ * D_; idx += 256) {
        int n = idx >> 9, d = idx & (D_ - 1);
        xs[n][d] = transposed ? src[tb + (long)n * T_ * D_ + d]
                              : src[((long)g * N_ + n) * D_ + d];
    }
    __syncthreads();
    for (int task = tid; task < N_ * 64; task += 256) {
        int n = task >> 6, k8 = task & 63, d0 = k8 << 3;
        float m[8];
        #pragma unroll
        for (int i = 0; i < 8; i++) m[i] = (1.0f - ALPHA) * xs[n][d0 + i];
        #pragma unroll
        for (int j = 0; j < N_; j++) {
            float a = ALPHA * sadj[n][j];
            #pragma unroll
            for (int i = 0; i < 8; i++) m[i] = fmaf(a, xs[j][d0 + i], m[i]);
        }
        union { uint4 q; __nv_bfloat16 h[8]; } H, L;
        #pragma unroll
        for (int i = 0; i < 8; i++) {
            H.h[i] = __float2bfloat16(m[i]);
            L.h[i] = __float2bfloat16(m[i] - __bfloat162float(H.h[i]));
        }
        int r = g * N_ + n;
        int mt = r >> 7, rl = r & 127;
        size_t blk = (size_t)mt * KCHUNKS + (k8 >> 3);
        uint32_t off = swz((uint32_t)(rl * 128 + (k8 & 7) * 16));
        *(uint4*)(g_ahi + blk * ATILE_BYTES + off) = H.q;
        *(uint4*)(g_alo + blk * ATILE_BYTES + off) = L.q;
    }
}

// ---------------- stage 4: bf16 mma.sync GEMM, y = A@W (3-term split) -------
#define STAGE_BYTES 65536
#define GEMM_SMEM_DYN (2 * STAGE_BYTES + 1024)

__global__ __launch_bounds__(256, 1)
void gemm_kernel(const unsigned char* __restrict__ gAh,
                 const unsigned char* __restrict__ gAl,
                 const unsigned char* __restrict__ gBh,
                 const unsigned char* __restrict__ gBl,
                 float* __restrict__ y)
{
    extern __shared__ unsigned char smraw[];
    __shared__ __align__(8) unsigned long long s_mbar[2];

    const int tid = threadIdx.x, wid = tid >> 5, lane = tid & 31;
    const int wm = wid >> 1, wn = wid & 1;
    const int mtile = blockIdx.x >> 2, nt = blockIdx.x & 3;

    const uint32_t base = (smem_u32(smraw) + 1023) & ~1023u;
    const uint32_t mb0 = smem_u32(&s_mbar[0]);
    const uint32_t mb1 = mb0 + 8;
    if (tid == 0) { MBAR_INIT(mb0, 1); MBAR_INIT(mb1, 1); }
    __syncthreads();

    const unsigned char* pAh = gAh + (size_t)mtile * KCHUNKS * ATILE_BYTES;
    const unsigned char* pAl = gAl + (size_t)mtile * KCHUNKS * ATILE_BYTES;
    const unsigned char* pBh = gBh + (size_t)nt * BTILE_BYTES;
    const unsigned char* pBl = gBl + (size_t)nt * BTILE_BYTES;

    const uint32_t a_row = wm * 32 + (lane & 15);
    const uint32_t a_rowoff = a_row * 128;
    const uint32_t a_klane = (uint32_t)(lane >> 4) << 4;
    const uint32_t b_row = wn * 64 + ((lane >> 4) << 3) + (lane & 7);
    const uint32_t b_rowoff = b_row * 128;
    const uint32_t b_klane = (uint32_t)((lane >> 3) & 1) << 4;
    const uint32_t cswz = (uint32_t)(lane & 7) << 4;

    float acc[2][8][4];
    #pragma unroll
    for (int ms = 0; ms < 2; ms++)
        #pragma unroll
        for (int ns = 0; ns < 8; ns++)
            #pragma unroll
            for (int q = 0; q < 4; q++) acc[ms][ns][q] = 0.0f;

    if (tid == 0) {
        MBAR_EXPECT(mb0, (uint32_t)STAGE_BYTES);
        bulk_g2s(base,         pAh, ATILE_BYTES, mb0);
        bulk_g2s(base + 16384, pAl, ATILE_BYTES, mb0);
        bulk_g2s(base + 32768, pBh, BTILE_BYTES, mb0);
        bulk_g2s(base + 49152, pBl, BTILE_BYTES, mb0);
    }

    for (int kc = 0; kc < KCHUNKS; kc++) {
        MBAR_WAIT((kc & 1) ? mb1 : mb0, (kc >> 1) & 1);
        __syncthreads();
        if (tid == 0 && kc + 1 < KCHUNKS) {
            int kn = kc + 1;
            uint32_t st = base + (kn & 1) * STAGE_BYTES;
            uint32_t mb = (kn & 1) ? mb1 : mb0;
            MBAR_EXPECT(mb, (uint32_t)STAGE_BYTES);
            bulk_g2s(st,         pAh + (size_t)kn * ATILE_BYTES, ATILE_BYTES, mb);
            bulk_g2s(st + 16384, pAl + (size_t)kn * ATILE_BYTES, ATILE_BYTES, mb);
            bulk_g2s(st + 32768, pBh + (size_t)kn * NTILES * BTILE_BYTES, BTILE_BYTES, mb);
            bulk_g2s(st + 49152, pBl + (size_t)kn * NTILES * BTILE_BYTES, BTILE_BYTES, mb);
        }
        const uint32_t st = base + (kc & 1) * STAGE_BYTES;
        const uint32_t sAh = st, sAl = st + 16384, sBh = st + 32768, sBl = st + 49152;

        #pragma unroll
        for (int ks = 0; ks < 4; ks++) {
            const uint32_t akb = ((uint32_t)(ks * 32) + a_klane) ^ cswz;
            const uint32_t bkb = ((uint32_t)(ks * 32) + b_klane) ^ cswz;
            uint32_t ah[2][4], al[2][4];
            LDX4(ah[0], sAh + a_rowoff + akb);
            LDX4(ah[1], sAh + a_rowoff + 2048 + akb);
            LDX4(al[0], sAl + a_rowoff + akb);
            LDX4(al[1], sAl + a_rowoff + 2048 + akb);
            uint32_t bh[4][4], bl[4][4];
            #pragma unroll
            for (int nb = 0; nb < 4; nb++) {
                LDX4(bh[nb], sBh + b_rowoff + nb * 2048 + bkb);
                LDX4(bl[nb], sBl + b_rowoff + nb * 2048 + bkb);
            }
            #pragma unroll
            for (int ms = 0; ms < 2; ms++) {
                #pragma unroll
                for (int ns = 0; ns < 8; ns++) {
                    const uint32_t* BH = &bh[ns >> 1][(ns & 1) * 2];
                    const uint32_t* BL = &bl[ns >> 1][(ns & 1) * 2];
                    MMA(acc[ms][ns], ah[ms], BH[0], BH[1]);
                    MMA(acc[ms][ns], ah[ms], BL[0], BL[1]);
                    MMA(acc[ms][ns], al[ms], BH[0], BH[1]);
                }
            }
        }
    }

    const int mrow = mtile * 128 + wm * 32;
    const int ncol = nt * 128 + wn * 64;
    #pragma unroll
    for (int ms = 0; ms < 2; ms++) {
        const int r0 = mrow + ms * 16 + (lane >> 2);
        const int r1 = r0 + 8;
        #pragma unroll
        for (int ns = 0; ns < 8; ns++) {
            const int c = ncol + ns * 8 + (lane & 3) * 2;
            if (r0 < NROWS)
                *(float2*)(y + (size_t)r0 * D_ + c) = make_float2(acc[ms][ns][0], acc[ms][ns][1]);
            if (r1 < NROWS)
                *(float2*)(y + (size_t)r1 * D_ + c) = make_float2(acc[ms][ns][2], acc[ms][ns][3]);
        }
    }
}

// ---------------- stage 5: bias + residual + LayerNorm + exact GELU ---------
__global__ __launch_bounds__(256)
void ln_kernel(const float* __restrict__ y,
               const float* __restrict__ res, int res_trans,
               float* __restrict__ dst, int dst_trans,
               const float* __restrict__ gamma, const float* __restrict__ beta,
               const float* __restrict__ bias, int layer)
{
    int row = blockIdx.x * 8 + (threadIdx.x >> 5);
    int lane = threadIdx.x & 31;
    if (row >= NROWS) return;
    long toff = 0;
    if (res_trans | dst_trans) {
        int g = row / N_, n = row - g * N_;
        int bb = g / T_, tt = g - bb * T_;
        toff = ((long)(bb * N_ + n) * T_ + tt) * D_;
    }
    const float* rp = res + (res_trans ? toff : (long)row * D_);
    float* dp = dst + (dst_trans ? toff : (long)row * D_);
    const float* yp = y + (long)row * D_;
    const float* bp = bias + layer * D_;

    float v[16];
    float sum = 0.0f, sq = 0.0f;
    #pragma unroll
    for (int i = 0; i < 4; i++) {
        int c = lane * 4 + i * 128;
        float4 a = *(const float4*)(yp + c);
        float4 r4 = *(const float4*)(rp + c);
        float4 b4 = *(const float4*)(bp + c);
        float t0 = a.x + b4.x + r4.x, t1 = a.y + b4.y + r4.y;
        float t2 = a.z + b4.z + r4.z, t3 = a.w + b4.w + r4.w;
        v[i*4+0] = t0; v[i*4+1] = t1; v[i*4+2] = t2; v[i*4+3] = t3;
        sum += t0 + t1 + t2 + t3;
        sq = fmaf(t0, t0, sq); sq = fmaf(t1, t1, sq);
        sq = fmaf(t2, t2, sq); sq = fmaf(t3, t3, sq);
    }
    #pragma unroll
    for (int o = 16; o; o >>= 1) {
        sum += __shfl_xor_sync(0xffffffffu, sum, o);
        sq  += __shfl_xor_sync(0xffffffffu, sq, o);
    }
    float mu = sum * (1.0f / D_);
    float var = sq * (1.0f / D_) - mu * mu;
    float rstd = rsqrtf(var + LN_EPS);
    #pragma unroll
    for (int i = 0; i < 4; i++) {
        int c = lane * 4 + i * 128;
        float4 g4 = *(const float4*)(gamma + layer * D_ + c);
        float4 be4 = *(const float4*)(beta + layer * D_ + c);
        float o0 = fmaf((v[i*4+0] - mu) * rstd, g4.x, be4.x);
        float o1 = fmaf((v[i*4+1] - mu) * rstd, g4.y, be4.y);
        float o2 = fmaf((v[i*4+2] - mu) * rstd, g4.z, be4.z);
        float o3 = fmaf((v[i*4+3] - mu) * rstd, g4.w, be4.w);
        o0 = 0.5f * o0 * (1.0f + erff(o0 * 0.70710678118654752f));
        o1 = 0.5f * o1 * (1.0f + erff(o1 * 0.70710678118654752f));
        o2 = 0.5f * o2 * (1.0f + erff(o2 * 0.70710678118654752f));
        o3 = 0.5f * o3 * (1.0f + erff(o3 * 0.70710678118654752f));
        *(float4*)(dp + c) = make_float4(o0, o1, o2, o3);
    }
}

// ---------------- launch -----------------------------------------------------
extern "C" void kernel_launch(void* const* d_in, const int* in_sizes, int n_in,
                              void* d_out, int out_size)
{
    const float* features  = (const float*)d_in[0];
    const float* adjacency = (const float*)d_in[1];
    const float* edge_w    = (const float*)d_in[2];
    const float* edge_b    = (const float*)d_in[3];
    const float* W         = (const float*)d_in[4];
    const float* bias      = (const float*)d_in[5];
    const float* gamma     = (const float*)d_in[6];
    const float* beta      = (const float*)d_in[7];
    float* out = (float*)d_out;

    unsigned char *ahi, *alo, *bhi, *blo;
    float *yv, *state;
    cudaGetSymbolAddress((void**)&ahi, g_ahi);
    cudaGetSymbolAddress((void**)&alo, g_alo);
    cudaGetSymbolAddress((void**)&bhi, g_bhi);
    cudaGetSymbolAddress((void**)&blo, g_blo);
    cudaGetSymbolAddress((void**)&yv, g_y);
    cudaGetSymbolAddress((void**)&state, g_state);

    cudaFuncSetAttribute(gemm_kernel, cudaFuncAttributeMaxDynamicSharedMemorySize,
                         GEMM_SMEM_DYN);

    adj_kernel<<<NGRAPH, 128>>>(adjacency, edge_w, edge_b);
    wconv_kernel<<<256, 256>>>(W);

    const size_t bl_layer = (size_t)KCHUNKS * NTILES * BTILE_BYTES;

    // layer 0
    mix_kernel<<<NGRAPH, 256>>>(features, 1);
    gemm_kernel<<<MTILES * NTILES, 256, GEMM_SMEM_DYN>>>(ahi, alo, bhi, blo, yv);
    ln_kernel<<<(NROWS + 7) / 8, 256>>>(yv, features, 1, state, 0,
                                        gamma, beta, bias, 0);
    // layer 1 (FIX: pass state pointer, not nullptr)
    mix_kernel<<<NGRAPH, 256>>>(state, 0);
    gemm_kernel<<<MTILES * NTILES, 256, GEMM_SMEM_DYN>>>(ahi, alo,
                                                         bhi + bl_layer, blo + bl_layer, yv);
    ln_kernel<<<(NROWS + 7) / 8, 256>>>(yv, state, 0, out, 1,
                                        gamma, beta, bias, 1);
}